// round 9
// baseline (speedup 1.0000x reference)
#include <cuda_runtime.h>
#include <cuda_fp16.h>
#include <math.h>
#include <stdint.h>

#define BATCH 2
#define SEQ   2048
#define NH    16
#define HD    64
#define HID   1024            // NH*HD
#define MROWS (BATCH*SEQ)     // 4096

// Scratch (no allocations allowed)
__device__ float g_q[MROWS * HID];
__device__ float g_k[MROWS * HID];
__device__ float g_v[MROWS * HID];
__device__ float g_cos[SEQ * 32];
__device__ float g_sin[SEQ * 32];

__device__ __forceinline__ void mma_f16(float c[4], const uint32_t a[4],
                                        uint32_t b0, uint32_t b1) {
    asm volatile(
        "mma.sync.aligned.m16n8k16.row.col.f32.f16.f16.f32 "
        "{%0,%1,%2,%3},{%4,%5,%6,%7},{%8,%9},{%0,%1,%2,%3};"
        : "+f"(c[0]), "+f"(c[1]), "+f"(c[2]), "+f"(c[3])
        : "r"(a[0]), "r"(a[1]), "r"(a[2]), "r"(a[3]), "r"(b0), "r"(b1));
}

__device__ __forceinline__ uint32_t packh2(float lo, float hi) {
    __half2 h = __floats2half2_rn(lo, hi);
    return *(uint32_t*)&h;
}

// Bank-spread swizzle key for [row][pair] half2 layouts (32 words/row).
__device__ __forceinline__ int FSW(int d) { return ((d & 7) << 2) | ((d >> 3) & 3); }

// ---------------------------------------------------------------------------
// QKV projection, fp16 m16n8k16: Y = X @ W^T.
// X[M,K] row-major, W[N,K] row-major. blockIdx.z selects q/k/v.
// Block tile 128x128, K-step 32. 8 warps in 4x2 (warp tile 32x64).
// SMEM: half2 words, 16 pairs/row padded to 20 (bank stride 20 => rows 0..7
// of any g-lane group land in distinct banks; no XOR math needed).
// ---------------------------------------------------------------------------
#define QPAD 20
__global__ __launch_bounds__(256)
void qkv_gemm(const float* __restrict__ X,
              const float* __restrict__ Wq,
              const float* __restrict__ Wk,
              const float* __restrict__ Wv) {
    __shared__ uint32_t As2[128 * QPAD];
    __shared__ uint32_t Bs2[128 * QPAD];

    const float* W = (blockIdx.z == 0) ? Wq : (blockIdx.z == 1) ? Wk : Wv;
    float* Y       = (blockIdx.z == 0) ? g_q : (blockIdx.z == 1) ? g_k : g_v;

    const int m0 = blockIdx.y * 128;
    const int n0 = blockIdx.x * 128;
    const int tid  = threadIdx.x;
    const int warp = tid >> 5;
    const int lane = tid & 31;
    const int g = lane >> 2;
    const int t = lane & 3;
    const int wm0 = (warp >> 1) * 32;   // 0,32,64,96
    const int wn0 = (warp & 1) * 64;    // 0,64

    float acc[2][8][4];
#pragma unroll
    for (int mt = 0; mt < 2; mt++)
#pragma unroll
        for (int nt = 0; nt < 8; nt++)
#pragma unroll
            for (int e = 0; e < 4; e++) acc[mt][nt][e] = 0.0f;

    for (int k0 = 0; k0 < HID; k0 += 32) {
        // Stage A and B tiles: 128 rows x 32 cols fp32 -> half2 pairs
#pragma unroll
        for (int u = 0; u < 4; u++) {
            int idx = tid + u * 256;
            int row = idx >> 3;          // 0..127
            int c4  = (idx & 7) * 4;     // 0..28
            int w0  = row * QPAD + (c4 >> 1);
            float4 xa = *(const float4*)&X[(size_t)(m0 + row) * HID + k0 + c4];
            As2[w0]     = packh2(xa.x, xa.y);
            As2[w0 + 1] = packh2(xa.z, xa.w);
            float4 wb = *(const float4*)&W[(size_t)(n0 + row) * HID + k0 + c4];
            Bs2[w0]     = packh2(wb.x, wb.y);
            Bs2[w0 + 1] = packh2(wb.z, wb.w);
        }
        __syncthreads();

#pragma unroll
        for (int kb = 0; kb < 2; kb++) {
            uint32_t a[2][4];
#pragma unroll
            for (int mt = 0; mt < 2; mt++) {
                int ra = (wm0 + mt * 16 + g) * QPAD;
                int rb = (wm0 + mt * 16 + 8 + g) * QPAD;
                a[mt][0] = As2[ra + kb * 8 + t];
                a[mt][1] = As2[rb + kb * 8 + t];
                a[mt][2] = As2[ra + kb * 8 + 4 + t];
                a[mt][3] = As2[rb + kb * 8 + 4 + t];
            }
#pragma unroll
            for (int nt = 0; nt < 8; nt++) {
                int rc = (wn0 + nt * 8 + g) * QPAD;
                uint32_t b0 = Bs2[rc + kb * 8 + t];
                uint32_t b1 = Bs2[rc + kb * 8 + 4 + t];
                mma_f16(acc[0][nt], a[0], b0, b1);
                mma_f16(acc[1][nt], a[1], b0, b1);
            }
        }
        __syncthreads();
    }

#pragma unroll
    for (int mt = 0; mt < 2; mt++)
#pragma unroll
        for (int nt = 0; nt < 8; nt++) {
            int row0 = m0 + wm0 + mt * 16 + g;
            int col  = n0 + wn0 + nt * 8 + 2 * t;
            *(float2*)&Y[(size_t)row0 * HID + col] =
                make_float2(acc[mt][nt][0], acc[mt][nt][1]);
            *(float2*)&Y[(size_t)(row0 + 8) * HID + col] =
                make_float2(acc[mt][nt][2], acc[mt][nt][3]);
        }
}

// ---------------------------------------------------------------------------
// RoPE tables (apply is fused into attention staging)
// ---------------------------------------------------------------------------
__global__ void rope_table() {
    int idx = blockIdx.x * blockDim.x + threadIdx.x;
    if (idx >= SEQ * 32) return;
    int s = idx >> 5;
    int j = idx & 31;
    double inv = pow(10000.0, -(double)j / 32.0);
    double a = (double)s * inv;
    g_cos[idx] = (float)cos(a);
    g_sin[idx] = (float)sin(a);
}

// ---------------------------------------------------------------------------
// Flash attention, fp16 m16n8k16 (unchanged from round 6 — known good).
// ---------------------------------------------------------------------------
__global__ __launch_bounds__(128)
void attn_kernel(float* __restrict__ out) {
    __shared__ uint32_t sh[4096];     // 16 KB
    uint32_t* Kh = sh;                // 2048 words
    uint32_t* Vh = sh + 2048;         // 2048 words

    const int tid  = threadIdx.x;
    const int warp = tid >> 5;
    const int lane = tid & 31;
    const int g = lane >> 2;
    const int t = lane & 3;
    const int h = blockIdx.y & (NH - 1);
    const int b = blockIdx.y >> 4;
    const int q0 = blockIdx.x * 128;

    const float* qptr = g_q + (size_t)b * SEQ * HID + h * HD;
    const float* kptr = g_k + (size_t)b * SEQ * HID + h * HD;
    const float* vptr = g_v + (size_t)b * SEQ * HID + h * HD;

    // ---- Stage Q (RoPE + 1/8 scale) into this warp's scratch, grab frags ----
    uint32_t* Qs = sh + warp * 1024;  // 32 rows x 32 words
#pragma unroll
    for (int it = 0; it < 8; it++) {
        int idx2 = lane + it * 32;
        int dg = idx2 & 7;
        int r  = idx2 >> 3;
        int row = q0 + warp * 32 + r;
        const float* qr = qptr + (size_t)row * HID;
        float4 lo = *(const float4*)&qr[dg * 4];
        float4 hi = *(const float4*)&qr[dg * 4 + 32];
        float4 cz = *(const float4*)&g_cos[row * 32 + dg * 4];
        float4 sz = *(const float4*)&g_sin[row * 32 + dg * 4];
        float a0 = (lo.x * cz.x - hi.x * sz.x) * 0.125f;
        float a1 = (lo.y * cz.y - hi.y * sz.y) * 0.125f;
        float a2 = (lo.z * cz.z - hi.z * sz.z) * 0.125f;
        float a3 = (lo.w * cz.w - hi.w * sz.w) * 0.125f;
        float b0 = (hi.x * cz.x + lo.x * sz.x) * 0.125f;
        float b1 = (hi.y * cz.y + lo.y * sz.y) * 0.125f;
        float b2 = (hi.z * cz.z + lo.z * sz.z) * 0.125f;
        float b3 = (hi.w * cz.w + lo.w * sz.w) * 0.125f;
        int fr = FSW(r);
        Qs[r * 32 + ((dg * 2 + 0)  ^ fr)] = packh2(a0, a1);
        Qs[r * 32 + ((dg * 2 + 1)  ^ fr)] = packh2(a2, a3);
        Qs[r * 32 + ((dg * 2 + 16) ^ fr)] = packh2(b0, b1);
        Qs[r * 32 + ((dg * 2 + 17) ^ fr)] = packh2(b2, b3);
    }
    __syncwarp();
    uint32_t qa[2][4][4];
#pragma unroll
    for (int mt = 0; mt < 2; mt++) {
        int ra = mt * 16 + g, rb = mt * 16 + 8 + g;
        int fa = FSW(ra), fb = FSW(rb);
#pragma unroll
        for (int kb = 0; kb < 4; kb++) {
            qa[mt][kb][0] = Qs[ra * 32 + ((kb * 8 + t)     ^ fa)];
            qa[mt][kb][1] = Qs[rb * 32 + ((kb * 8 + t)     ^ fb)];
            qa[mt][kb][2] = Qs[ra * 32 + ((kb * 8 + t + 4) ^ fa)];
            qa[mt][kb][3] = Qs[rb * 32 + ((kb * 8 + t + 4) ^ fb)];
        }
    }

    float m_i[2][2], l_i[2][2];
    float o[2][8][4];
#pragma unroll
    for (int mt = 0; mt < 2; mt++) {
        m_i[mt][0] = m_i[mt][1] = -1e30f;
        l_i[mt][0] = l_i[mt][1] = 0.0f;
#pragma unroll
        for (int nb = 0; nb < 8; nb++)
#pragma unroll
            for (int e = 0; e < 4; e++) o[mt][nb][e] = 0.0f;
    }

    for (int k0 = 0; k0 < SEQ; k0 += 64) {
        __syncthreads();

        // ---- Stage K (with RoPE) ----
#pragma unroll
        for (int u = 0; u < 4; u++) {
            int idx = tid + u * 128;
            int dg = idx & 7;
            int r  = idx >> 3;
            int pos = k0 + r;
            const float* kr = kptr + (size_t)pos * HID;
            float4 lo = *(const float4*)&kr[dg * 4];
            float4 hi = *(const float4*)&kr[dg * 4 + 32];
            float4 cz = *(const float4*)&g_cos[pos * 32 + dg * 4];
            float4 sz = *(const float4*)&g_sin[pos * 32 + dg * 4];
            int fr = FSW(r);
            Kh[r * 32 + ((dg * 2 + 0)  ^ fr)] =
                packh2(lo.x * cz.x - hi.x * sz.x, lo.y * cz.y - hi.y * sz.y);
            Kh[r * 32 + ((dg * 2 + 1)  ^ fr)] =
                packh2(lo.z * cz.z - hi.z * sz.z, lo.w * cz.w - hi.w * sz.w);
            Kh[r * 32 + ((dg * 2 + 16) ^ fr)] =
                packh2(hi.x * cz.x + lo.x * sz.x, hi.y * cz.y + lo.y * sz.y);
            Kh[r * 32 + ((dg * 2 + 17) ^ fr)] =
                packh2(hi.z * cz.z + lo.z * sz.z, hi.w * cz.w + lo.w * sz.w);
        }
        // ---- Stage V (transposed: [dim][keypair]) ----
#pragma unroll
        for (int u = 0; u < 4; u++) {
            int idx = tid + u * 128;
            int c4 = (idx & 15) * 4;
            int kp = idx >> 4;
            const float* v0 = vptr + (size_t)(k0 + 2 * kp) * HID;
            float4 va = *(const float4*)&v0[c4];
            float4 vb = *(const float4*)&v0[HID + c4];
            Vh[(c4 + 0) * 32 + (kp ^ FSW(c4 + 0))] = packh2(va.x, vb.x);
            Vh[(c4 + 1) * 32 + (kp ^ FSW(c4 + 1))] = packh2(va.y, vb.y);
            Vh[(c4 + 2) * 32 + (kp ^ FSW(c4 + 2))] = packh2(va.z, vb.z);
            Vh[(c4 + 3) * 32 + (kp ^ FSW(c4 + 3))] = packh2(va.w, vb.w);
        }
        __syncthreads();

        // ---- S = Q @ K^T : 32x64 per warp ----
        float s[2][8][4];
#pragma unroll
        for (int mt = 0; mt < 2; mt++)
#pragma unroll
            for (int nb = 0; nb < 8; nb++)
#pragma unroll
                for (int e = 0; e < 4; e++) s[mt][nb][e] = 0.0f;

#pragma unroll
        for (int kb = 0; kb < 4; kb++) {
#pragma unroll
            for (int nb = 0; nb < 8; nb++) {
                int key = nb * 8 + g;
                int fk = FSW(key);
                uint32_t b0 = Kh[key * 32 + ((kb * 8 + t)     ^ fk)];
                uint32_t b1 = Kh[key * 32 + ((kb * 8 + t + 4) ^ fk)];
                mma_f16(s[0][nb], qa[0][kb], b0, b1);
                mma_f16(s[1][nb], qa[1][kb], b0, b1);
            }
        }

        // ---- Online softmax; pack P into fp16 A-frags (registers only) ----
        uint32_t pa[2][4][4];
#pragma unroll
        for (int mt = 0; mt < 2; mt++) {
#pragma unroll
            for (int hh = 0; hh < 2; hh++) {
                const int e0 = hh * 2;
                float mx = -1e30f;
#pragma unroll
                for (int nb = 0; nb < 8; nb++)
                    mx = fmaxf(mx, fmaxf(s[mt][nb][e0], s[mt][nb][e0 + 1]));
                mx = fmaxf(mx, __shfl_xor_sync(0xffffffffu, mx, 1));
                mx = fmaxf(mx, __shfl_xor_sync(0xffffffffu, mx, 2));
                float mnew = fmaxf(m_i[mt][hh], mx);
                float corr = __expf(m_i[mt][hh] - mnew);
                float rs = 0.0f;
#pragma unroll
                for (int nb = 0; nb < 8; nb++) {
                    float p0 = __expf(s[mt][nb][e0]     - mnew);
                    float p1 = __expf(s[mt][nb][e0 + 1] - mnew);
                    rs += p0 + p1;
                    s[mt][nb][e0]     = p0;
                    s[mt][nb][e0 + 1] = p1;
                }
                rs += __shfl_xor_sync(0xffffffffu, rs, 1);
                rs += __shfl_xor_sync(0xffffffffu, rs, 2);
                l_i[mt][hh] = l_i[mt][hh] * corr + rs;
                m_i[mt][hh] = mnew;
#pragma unroll
                for (int nb = 0; nb < 8; nb++) {
                    o[mt][nb][e0]     *= corr;
                    o[mt][nb][e0 + 1] *= corr;
                }
            }
#pragma unroll
            for (int kb = 0; kb < 4; kb++) {
                pa[mt][kb][0] = packh2(s[mt][2 * kb][0],     s[mt][2 * kb][1]);
                pa[mt][kb][1] = packh2(s[mt][2 * kb][2],     s[mt][2 * kb][3]);
                pa[mt][kb][2] = packh2(s[mt][2 * kb + 1][0], s[mt][2 * kb + 1][1]);
                pa[mt][kb][3] = packh2(s[mt][2 * kb + 1][2], s[mt][2 * kb + 1][3]);
            }
        }

        // ---- ctx += P @ V : 32x64 per warp ----
#pragma unroll
        for (int kb = 0; kb < 4; kb++) {
#pragma unroll
            for (int nb = 0; nb < 8; nb++) {
                int dim = nb * 8 + g;
                int fd = FSW(dim);
                uint32_t b0 = Vh[dim * 32 + ((kb * 8 + t)     ^ fd)];
                uint32_t b1 = Vh[dim * 32 + ((kb * 8 + t + 4) ^ fd)];
                mma_f16(o[0][nb], pa[0][kb], b0, b1);
                mma_f16(o[1][nb], pa[1][kb], b0, b1);
            }
        }
    }

    // ---- Normalize and write out[b, s, h*64 + d] ----
#pragma unroll
    for (int mt = 0; mt < 2; mt++)
#pragma unroll
        for (int hh = 0; hh < 2; hh++) {
            float inv_l = 1.0f / l_i[mt][hh];
            int row = q0 + warp * 32 + mt * 16 + g + 8 * hh;
#pragma unroll
            for (int nb = 0; nb < 8; nb++) {
                size_t base = (size_t)(b * SEQ + row) * HID + h * HD + nb * 8 + 2 * t;
                *(float2*)&out[base] = make_float2(o[mt][nb][2 * hh]     * inv_l,
                                                   o[mt][nb][2 * hh + 1] * inv_l);
            }
        }
}

// ---------------------------------------------------------------------------
extern "C" void kernel_launch(void* const* d_in, const int* in_sizes, int n_in,
                              void* d_out, int out_size) {
    const float* X  = (const float*)d_in[0];
    const float* Wq = (const float*)d_in[1];
    const float* Wk = (const float*)d_in[2];
    const float* Wv = (const float*)d_in[3];
    float* out = (float*)d_out;

    qkv_gemm<<<dim3(HID / 128, MROWS / 128, 3), 256>>>(X, Wq, Wk, Wv);
    rope_table<<<(SEQ * 32 + 255) / 256, 256>>>();
    attn_kernel<<<dim3(SEQ / 128, NH * BATCH), 128>>>(out);
}

// round 10
// speedup vs baseline: 1.0032x; 1.0032x over previous
#include <cuda_runtime.h>
#include <cuda_fp16.h>
#include <math.h>
#include <stdint.h>

#define BATCH 2
#define SEQ   2048
#define NH    16
#define HD    64
#define HID   1024            // NH*HD
#define MROWS (BATCH*SEQ)     // 4096

// Scratch (no allocations allowed)
__device__ float g_q[MROWS * HID];
__device__ float g_k[MROWS * HID];
__device__ float g_v[MROWS * HID];
__device__ float g_cos[SEQ * 32];
__device__ float g_sin[SEQ * 32];

__device__ __forceinline__ void mma_f16(float c[4], const uint32_t a[4],
                                        uint32_t b0, uint32_t b1) {
    asm volatile(
        "mma.sync.aligned.m16n8k16.row.col.f32.f16.f16.f32 "
        "{%0,%1,%2,%3},{%4,%5,%6,%7},{%8,%9},{%0,%1,%2,%3};"
        : "+f"(c[0]), "+f"(c[1]), "+f"(c[2]), "+f"(c[3])
        : "r"(a[0]), "r"(a[1]), "r"(a[2]), "r"(a[3]), "r"(b0), "r"(b1));
}

__device__ __forceinline__ uint32_t packh2(float lo, float hi) {
    __half2 h = __floats2half2_rn(lo, hi);
    return *(uint32_t*)&h;
}

// Bank-spread swizzle key for [row][pair] half2 layouts (32 words/row).
__device__ __forceinline__ int FSW(int d) { return ((d & 7) << 2) | ((d >> 3) & 3); }

// ---------------------------------------------------------------------------
// QKV projection, fp16 m16n8k16: Y = X @ W^T.
// X[M,K] row-major, W[N,K] row-major. blockIdx.z selects q/k/v.
// Block tile 128x128, K-step 32. 8 warps in 4x2 (warp tile 32x64).
// SMEM: half2 words, 16 pairs/row padded to 20 (bank stride 20 => rows 0..7
// of any g-lane group land in distinct banks; no XOR math needed).
// ---------------------------------------------------------------------------
#define QPAD 20
__global__ __launch_bounds__(256)
void qkv_gemm(const float* __restrict__ X,
              const float* __restrict__ Wq,
              const float* __restrict__ Wk,
              const float* __restrict__ Wv) {
    __shared__ uint32_t As2[128 * QPAD];
    __shared__ uint32_t Bs2[128 * QPAD];

    const float* W = (blockIdx.z == 0) ? Wq : (blockIdx.z == 1) ? Wk : Wv;
    float* Y       = (blockIdx.z == 0) ? g_q : (blockIdx.z == 1) ? g_k : g_v;

    const int m0 = blockIdx.y * 128;
    const int n0 = blockIdx.x * 128;
    const int tid  = threadIdx.x;
    const int warp = tid >> 5;
    const int lane = tid & 31;
    const int g = lane >> 2;
    const int t = lane & 3;
    const int wm0 = (warp >> 1) * 32;   // 0,32,64,96
    const int wn0 = (warp & 1) * 64;    // 0,64

    float acc[2][8][4];
#pragma unroll
    for (int mt = 0; mt < 2; mt++)
#pragma unroll
        for (int nt = 0; nt < 8; nt++)
#pragma unroll
            for (int e = 0; e < 4; e++) acc[mt][nt][e] = 0.0f;

    for (int k0 = 0; k0 < HID; k0 += 32) {
        // Stage A and B tiles: 128 rows x 32 cols fp32 -> half2 pairs
#pragma unroll
        for (int u = 0; u < 4; u++) {
            int idx = tid + u * 256;
            int row = idx >> 3;          // 0..127
            int c4  = (idx & 7) * 4;     // 0..28
            int w0  = row * QPAD + (c4 >> 1);
            float4 xa = *(const float4*)&X[(size_t)(m0 + row) * HID + k0 + c4];
            As2[w0]     = packh2(xa.x, xa.y);
            As2[w0 + 1] = packh2(xa.z, xa.w);
            float4 wb = *(const float4*)&W[(size_t)(n0 + row) * HID + k0 + c4];
            Bs2[w0]     = packh2(wb.x, wb.y);
            Bs2[w0 + 1] = packh2(wb.z, wb.w);
        }
        __syncthreads();

#pragma unroll
        for (int kb = 0; kb < 2; kb++) {
            uint32_t a[2][4];
#pragma unroll
            for (int mt = 0; mt < 2; mt++) {
                int ra = (wm0 + mt * 16 + g) * QPAD;
                int rb = (wm0 + mt * 16 + 8 + g) * QPAD;
                a[mt][0] = As2[ra + kb * 8 + t];
                a[mt][1] = As2[rb + kb * 8 + t];
                a[mt][2] = As2[ra + kb * 8 + 4 + t];
                a[mt][3] = As2[rb + kb * 8 + 4 + t];
            }
#pragma unroll
            for (int nt = 0; nt < 8; nt++) {
                int rc = (wn0 + nt * 8 + g) * QPAD;
                uint32_t b0 = Bs2[rc + kb * 8 + t];
                uint32_t b1 = Bs2[rc + kb * 8 + 4 + t];
                mma_f16(acc[0][nt], a[0], b0, b1);
                mma_f16(acc[1][nt], a[1], b0, b1);
            }
        }
        __syncthreads();
    }

#pragma unroll
    for (int mt = 0; mt < 2; mt++)
#pragma unroll
        for (int nt = 0; nt < 8; nt++) {
            int row0 = m0 + wm0 + mt * 16 + g;
            int col  = n0 + wn0 + nt * 8 + 2 * t;
            *(float2*)&Y[(size_t)row0 * HID + col] =
                make_float2(acc[mt][nt][0], acc[mt][nt][1]);
            *(float2*)&Y[(size_t)(row0 + 8) * HID + col] =
                make_float2(acc[mt][nt][2], acc[mt][nt][3]);
        }
}

// ---------------------------------------------------------------------------
// RoPE tables (apply is fused into attention staging)
// ---------------------------------------------------------------------------
__global__ void rope_table() {
    int idx = blockIdx.x * blockDim.x + threadIdx.x;
    if (idx >= SEQ * 32) return;
    int s = idx >> 5;
    int j = idx & 31;
    double inv = pow(10000.0, -(double)j / 32.0);
    double a = (double)s * inv;
    g_cos[idx] = (float)cos(a);
    g_sin[idx] = (float)sin(a);
}

// ---------------------------------------------------------------------------
// Flash attention, fp16 m16n8k16 (unchanged from round 6 — known good).
// ---------------------------------------------------------------------------
__global__ __launch_bounds__(128)
void attn_kernel(float* __restrict__ out) {
    __shared__ uint32_t sh[4096];     // 16 KB
    uint32_t* Kh = sh;                // 2048 words
    uint32_t* Vh = sh + 2048;         // 2048 words

    const int tid  = threadIdx.x;
    const int warp = tid >> 5;
    const int lane = tid & 31;
    const int g = lane >> 2;
    const int t = lane & 3;
    const int h = blockIdx.y & (NH - 1);
    const int b = blockIdx.y >> 4;
    const int q0 = blockIdx.x * 128;

    const float* qptr = g_q + (size_t)b * SEQ * HID + h * HD;
    const float* kptr = g_k + (size_t)b * SEQ * HID + h * HD;
    const float* vptr = g_v + (size_t)b * SEQ * HID + h * HD;

    // ---- Stage Q (RoPE + 1/8 scale) into this warp's scratch, grab frags ----
    uint32_t* Qs = sh + warp * 1024;  // 32 rows x 32 words
#pragma unroll
    for (int it = 0; it < 8; it++) {
        int idx2 = lane + it * 32;
        int dg = idx2 & 7;
        int r  = idx2 >> 3;
        int row = q0 + warp * 32 + r;
        const float* qr = qptr + (size_t)row * HID;
        float4 lo = *(const float4*)&qr[dg * 4];
        float4 hi = *(const float4*)&qr[dg * 4 + 32];
        float4 cz = *(const float4*)&g_cos[row * 32 + dg * 4];
        float4 sz = *(const float4*)&g_sin[row * 32 + dg * 4];
        float a0 = (lo.x * cz.x - hi.x * sz.x) * 0.125f;
        float a1 = (lo.y * cz.y - hi.y * sz.y) * 0.125f;
        float a2 = (lo.z * cz.z - hi.z * sz.z) * 0.125f;
        float a3 = (lo.w * cz.w - hi.w * sz.w) * 0.125f;
        float b0 = (hi.x * cz.x + lo.x * sz.x) * 0.125f;
        float b1 = (hi.y * cz.y + lo.y * sz.y) * 0.125f;
        float b2 = (hi.z * cz.z + lo.z * sz.z) * 0.125f;
        float b3 = (hi.w * cz.w + lo.w * sz.w) * 0.125f;
        int fr = FSW(r);
        Qs[r * 32 + ((dg * 2 + 0)  ^ fr)] = packh2(a0, a1);
        Qs[r * 32 + ((dg * 2 + 1)  ^ fr)] = packh2(a2, a3);
        Qs[r * 32 + ((dg * 2 + 16) ^ fr)] = packh2(b0, b1);
        Qs[r * 32 + ((dg * 2 + 17) ^ fr)] = packh2(b2, b3);
    }
    __syncwarp();
    uint32_t qa[2][4][4];
#pragma unroll
    for (int mt = 0; mt < 2; mt++) {
        int ra = mt * 16 + g, rb = mt * 16 + 8 + g;
        int fa = FSW(ra), fb = FSW(rb);
#pragma unroll
        for (int kb = 0; kb < 4; kb++) {
            qa[mt][kb][0] = Qs[ra * 32 + ((kb * 8 + t)     ^ fa)];
            qa[mt][kb][1] = Qs[rb * 32 + ((kb * 8 + t)     ^ fb)];
            qa[mt][kb][2] = Qs[ra * 32 + ((kb * 8 + t + 4) ^ fa)];
            qa[mt][kb][3] = Qs[rb * 32 + ((kb * 8 + t + 4) ^ fb)];
        }
    }

    float m_i[2][2], l_i[2][2];
    float o[2][8][4];
#pragma unroll
    for (int mt = 0; mt < 2; mt++) {
        m_i[mt][0] = m_i[mt][1] = -1e30f;
        l_i[mt][0] = l_i[mt][1] = 0.0f;
#pragma unroll
        for (int nb = 0; nb < 8; nb++)
#pragma unroll
            for (int e = 0; e < 4; e++) o[mt][nb][e] = 0.0f;
    }

    for (int k0 = 0; k0 < SEQ; k0 += 64) {
        __syncthreads();

        // ---- Stage K (with RoPE) ----
#pragma unroll
        for (int u = 0; u < 4; u++) {
            int idx = tid + u * 128;
            int dg = idx & 7;
            int r  = idx >> 3;
            int pos = k0 + r;
            const float* kr = kptr + (size_t)pos * HID;
            float4 lo = *(const float4*)&kr[dg * 4];
            float4 hi = *(const float4*)&kr[dg * 4 + 32];
            float4 cz = *(const float4*)&g_cos[pos * 32 + dg * 4];
            float4 sz = *(const float4*)&g_sin[pos * 32 + dg * 4];
            int fr = FSW(r);
            Kh[r * 32 + ((dg * 2 + 0)  ^ fr)] =
                packh2(lo.x * cz.x - hi.x * sz.x, lo.y * cz.y - hi.y * sz.y);
            Kh[r * 32 + ((dg * 2 + 1)  ^ fr)] =
                packh2(lo.z * cz.z - hi.z * sz.z, lo.w * cz.w - hi.w * sz.w);
            Kh[r * 32 + ((dg * 2 + 16) ^ fr)] =
                packh2(hi.x * cz.x + lo.x * sz.x, hi.y * cz.y + lo.y * sz.y);
            Kh[r * 32 + ((dg * 2 + 17) ^ fr)] =
                packh2(hi.z * cz.z + lo.z * sz.z, hi.w * cz.w + lo.w * sz.w);
        }
        // ---- Stage V (transposed: [dim][keypair]) ----
#pragma unroll
        for (int u = 0; u < 4; u++) {
            int idx = tid + u * 128;
            int c4 = (idx & 15) * 4;
            int kp = idx >> 4;
            const float* v0 = vptr + (size_t)(k0 + 2 * kp) * HID;
            float4 va = *(const float4*)&v0[c4];
            float4 vb = *(const float4*)&v0[HID + c4];
            Vh[(c4 + 0) * 32 + (kp ^ FSW(c4 + 0))] = packh2(va.x, vb.x);
            Vh[(c4 + 1) * 32 + (kp ^ FSW(c4 + 1))] = packh2(va.y, vb.y);
            Vh[(c4 + 2) * 32 + (kp ^ FSW(c4 + 2))] = packh2(va.z, vb.z);
            Vh[(c4 + 3) * 32 + (kp ^ FSW(c4 + 3))] = packh2(va.w, vb.w);
        }
        __syncthreads();

        // ---- S = Q @ K^T : 32x64 per warp ----
        float s[2][8][4];
#pragma unroll
        for (int mt = 0; mt < 2; mt++)
#pragma unroll
            for (int nb = 0; nb < 8; nb++)
#pragma unroll
                for (int e = 0; e < 4; e++) s[mt][nb][e] = 0.0f;

#pragma unroll
        for (int kb = 0; kb < 4; kb++) {
#pragma unroll
            for (int nb = 0; nb < 8; nb++) {
                int key = nb * 8 + g;
                int fk = FSW(key);
                uint32_t b0 = Kh[key * 32 + ((kb * 8 + t)     ^ fk)];
                uint32_t b1 = Kh[key * 32 + ((kb * 8 + t + 4) ^ fk)];
                mma_f16(s[0][nb], qa[0][kb], b0, b1);
                mma_f16(s[1][nb], qa[1][kb], b0, b1);
            }
        }

        // ---- Online softmax; pack P into fp16 A-frags (registers only) ----
        uint32_t pa[2][4][4];
#pragma unroll
        for (int mt = 0; mt < 2; mt++) {
#pragma unroll
            for (int hh = 0; hh < 2; hh++) {
                const int e0 = hh * 2;
                float mx = -1e30f;
#pragma unroll
                for (int nb = 0; nb < 8; nb++)
                    mx = fmaxf(mx, fmaxf(s[mt][nb][e0], s[mt][nb][e0 + 1]));
                mx = fmaxf(mx, __shfl_xor_sync(0xffffffffu, mx, 1));
                mx = fmaxf(mx, __shfl_xor_sync(0xffffffffu, mx, 2));
                float mnew = fmaxf(m_i[mt][hh], mx);
                float corr = __expf(m_i[mt][hh] - mnew);
                float rs = 0.0f;
#pragma unroll
                for (int nb = 0; nb < 8; nb++) {
                    float p0 = __expf(s[mt][nb][e0]     - mnew);
                    float p1 = __expf(s[mt][nb][e0 + 1] - mnew);
                    rs += p0 + p1;
                    s[mt][nb][e0]     = p0;
                    s[mt][nb][e0 + 1] = p1;
                }
                rs += __shfl_xor_sync(0xffffffffu, rs, 1);
                rs += __shfl_xor_sync(0xffffffffu, rs, 2);
                l_i[mt][hh] = l_i[mt][hh] * corr + rs;
                m_i[mt][hh] = mnew;
#pragma unroll
                for (int nb = 0; nb < 8; nb++) {
                    o[mt][nb][e0]     *= corr;
                    o[mt][nb][e0 + 1] *= corr;
                }
            }
#pragma unroll
            for (int kb = 0; kb < 4; kb++) {
                pa[mt][kb][0] = packh2(s[mt][2 * kb][0],     s[mt][2 * kb][1]);
                pa[mt][kb][1] = packh2(s[mt][2 * kb][2],     s[mt][2 * kb][3]);
                pa[mt][kb][2] = packh2(s[mt][2 * kb + 1][0], s[mt][2 * kb + 1][1]);
                pa[mt][kb][3] = packh2(s[mt][2 * kb + 1][2], s[mt][2 * kb + 1][3]);
            }
        }

        // ---- ctx += P @ V : 32x64 per warp ----
#pragma unroll
        for (int kb = 0; kb < 4; kb++) {
#pragma unroll
            for (int nb = 0; nb < 8; nb++) {
                int dim = nb * 8 + g;
                int fd = FSW(dim);
                uint32_t b0 = Vh[dim * 32 + ((kb * 8 + t)     ^ fd)];
                uint32_t b1 = Vh[dim * 32 + ((kb * 8 + t + 4) ^ fd)];
                mma_f16(o[0][nb], pa[0][kb], b0, b1);
                mma_f16(o[1][nb], pa[1][kb], b0, b1);
            }
        }
    }

    // ---- Normalize and write out[b, s, h*64 + d] ----
#pragma unroll
    for (int mt = 0; mt < 2; mt++)
#pragma unroll
        for (int hh = 0; hh < 2; hh++) {
            float inv_l = 1.0f / l_i[mt][hh];
            int row = q0 + warp * 32 + mt * 16 + g + 8 * hh;
#pragma unroll
            for (int nb = 0; nb < 8; nb++) {
                size_t base = (size_t)(b * SEQ + row) * HID + h * HD + nb * 8 + 2 * t;
                *(float2*)&out[base] = make_float2(o[mt][nb][2 * hh]     * inv_l,
                                                   o[mt][nb][2 * hh + 1] * inv_l);
            }
        }
}

// ---------------------------------------------------------------------------
extern "C" void kernel_launch(void* const* d_in, const int* in_sizes, int n_in,
                              void* d_out, int out_size) {
    const float* X  = (const float*)d_in[0];
    const float* Wq = (const float*)d_in[1];
    const float* Wk = (const float*)d_in[2];
    const float* Wv = (const float*)d_in[3];
    float* out = (float*)d_out;

    qkv_gemm<<<dim3(HID / 128, MROWS / 128, 3), 256>>>(X, Wq, Wk, Wv);
    rope_table<<<(SEQ * 32 + 255) / 256, 256>>>();
    attn_kernel<<<dim3(SEQ / 128, NH * BATCH), 128>>>(out);
}